// round 16
// baseline (speedup 1.0000x reference)
#include <cuda_runtime.h>

// Attention_72447508349519 — algebraic collapse:
//   softmax rows sum to 1 and einsum('bqk,bvd->bqd') contracts k and v
//   independently, so out[b,q,d] = sum_n v[b,n,d] for every q.
//   R16: ONE persistent kernel (296 CTAs = 2/SM, co-resident), four stages
//   sequenced by device counters instead of kernel boundaries:
//     S1 stats+weighted colsums (proven k1 body, __ldcs x)
//     S2 fold groups -> s       (proven fold body, 16 CTAs)
//     S3 GEMV Wv -> vsum        (per (16-d tile, bg) unit)
//     S4 GEMV Wo + broadcast 64MB store (__stcs), starts per-bg as soon as
//        that bg's 64 S3 units finish -> stores overlap remaining GEMVs.
//   Counters self-reset by the last CTA -> graph-replay safe.
// Unused inputs: Wq,bq,Wk,bk.

#define BSZ   16
#define CDIM  1024
#define NPOS  1024
#define NGRP  32
#define GROWS 32
#define EPS   1e-5f

#define NCTA  296
#define NTHR  512
#define PPITCH 1028   // bank = (4*fj + gq) mod 32 -> all 32 lanes distinct

__device__ float g_P[BSZ * NGRP * CDIM];
__device__ float g_mean[BSZ * NGRP];
__device__ float g_rstd[BSZ * NGRP];
__device__ float g_s[BSZ * CDIM];
__device__ float g_vsum[BSZ * CDIM];
__device__ int d_done1[BSZ];   // per-batch S1 tile count (target 32)
__device__ int d_done2[BSZ];   // per-batch S2 flag (target 1)
__device__ int d_done3[8];     // per-bg S3 unit count (target 64)
__device__ int d_done4;        // CTA completion count (target NCTA)

__device__ __forceinline__ void wait_ge(volatile int* p, int target) {
    if (threadIdx.x == 0) { while (*p < target) __nanosleep(64); }
    __syncthreads();
    __threadfence();   // acquire: order subsequent loads after observed count
}

__device__ __forceinline__ void publish(int* p) {
    __threadfence();   // release: all this thread's prior stores
    __syncthreads();   // every thread has fenced
    if (threadIdx.x == 0) atomicAdd(p, 1);
}

__global__ __launch_bounds__(NTHR, 2) void mega(const float* __restrict__ x,
                                                const float* __restrict__ gamma,
                                                const float* __restrict__ beta,
                                                const float* __restrict__ Wv,
                                                const float* __restrict__ bv,
                                                const float* __restrict__ Wo,
                                                const float* __restrict__ bo,
                                                float* __restrict__ out) {
    const int cta = blockIdx.x;
    const int tid = threadIdx.x;
    const int wid = tid >> 5, lane = tid & 31;

    __shared__ float spw[8 * PPITCH];          // 32.9KB; S2 reuses as sgam; S3/4 as ss
    __shared__ float sg[GROWS];
    __shared__ float reds[16], redq[16];
    __shared__ float sGam[NGRP], sm2[NGRP], sr2[NGRP];
    __shared__ float sB[1];

    // ===================== Stage 1: stats + weighted colsums =====================
    for (int t = cta; t < BSZ * NGRP; t += NCTA) {
        const int b = t >> 5;
        const int g = t & 31;

        __syncthreads();                       // protect sg/spw reuse across tiles
        if (tid < GROWS) sg[tid] = gamma[g * GROWS + tid];
        __syncthreads();

        const int fj = tid & 7;
        const int gq = tid >> 3;
        const float w0 = sg[fj * 4 + 0], w1 = sg[fj * 4 + 1];
        const float w2 = sg[fj * 4 + 2], w3 = sg[fj * 4 + 3];

        const float* xb = x + (size_t)b * CDIM * NPOS + g * GROWS;
        float* mypw = spw + fj * PPITCH;

        float tsum = 0.f, tsq = 0.f;
        #pragma unroll
        for (int k0 = 0; k0 < 16; k0 += 8) {
            float4 tt[8];
            #pragma unroll
            for (int i = 0; i < 8; i++) {
                const int c = gq + 64 * (k0 + i);
                tt[i] = __ldcs(&reinterpret_cast<const float4*>(xb + (size_t)c * NPOS)[fj]);
            }
            #pragma unroll
            for (int i = 0; i < 8; i++) {
                const int c = gq + 64 * (k0 + i);
                const float4 v = tt[i];
                tsum += (v.x + v.y) + (v.z + v.w);
                tsq  += (v.x * v.x + v.y * v.y) + (v.z * v.z + v.w * v.w);
                mypw[c] = w0 * v.x + w1 * v.y + w2 * v.z + w3 * v.w;
            }
        }
        __syncthreads();

        float* Pout = g_P + (b * NGRP + g) * CDIM;
        #pragma unroll
        for (int m = 0; m < 2; m++) {
            const int c = tid + 512 * m;
            float acc = spw[c];
            #pragma unroll
            for (int f = 1; f < 8; f++) acc += spw[f * PPITCH + c];
            __stcs(&Pout[c], acc);
        }

        #pragma unroll
        for (int o = 16; o; o >>= 1) {
            tsum += __shfl_xor_sync(0xFFFFFFFFu, tsum, o);
            tsq  += __shfl_xor_sync(0xFFFFFFFFu, tsq,  o);
        }
        if (lane == 0) { reds[wid] = tsum; redq[wid] = tsq; }
        __syncthreads();
        if (tid == 0) {
            float S = 0.f, Q = 0.f;
            #pragma unroll
            for (int w = 0; w < 16; w++) { S += reds[w]; Q += redq[w]; }
            const float inv = 1.f / (float)(GROWS * CDIM);
            const float m = S * inv;
            const float var = Q * inv - m * m;
            g_mean[b * NGRP + g] = m;
            g_rstd[b * NGRP + g] = rsqrtf(var + EPS);
        }
        publish(&d_done1[b]);
    }

    // ===================== Stage 2: fold groups -> s (CTAs 0..15) ================
    if (cta < BSZ) {
        const int b = cta;
        wait_ge(&d_done1[b], NGRP);

        float* sgam = spw;                     // alias (S1 spw dead for this CTA)
        sgam[tid]       = gamma[tid];
        sgam[tid + 512] = gamma[tid + 512];
        float bb = beta[tid] + beta[tid + 512];
        #pragma unroll
        for (int o = 16; o; o >>= 1) bb += __shfl_xor_sync(0xFFFFFFFFu, bb, o);
        if (lane == 0) reds[wid] = bb;
        if (tid < NGRP) {
            sm2[tid] = __ldcg(&g_mean[b * NGRP + tid]);
            sr2[tid] = __ldcg(&g_rstd[b * NGRP + tid]);
        }
        __syncthreads();

        if (tid < NGRP) {
            float t = 0.f;
            #pragma unroll
            for (int j = 0; j < GROWS; j++) t += sgam[tid * GROWS + j];
            sGam[tid] = t;
        }
        if (tid == 0) {
            float t = 0.f;
            #pragma unroll
            for (int w = 0; w < 16; w++) t += reds[w];
            sB[0] = t;
        }
        __syncthreads();

        #pragma unroll
        for (int m = 0; m < 2; m++) {
            const int c = tid + 512 * m;
            float acc = sB[0];
            const float* Pb = g_P + b * NGRP * CDIM + c;
            #pragma unroll 8
            for (int gg = 0; gg < NGRP; gg++)
                acc += sr2[gg] * (__ldcg(&Pb[gg * CDIM]) - sm2[gg] * sGam[gg]);
            g_s[b * CDIM + c] = acc;
        }
        publish(&d_done2[b]);
    }

    // ===================== Stage 3: GEMV Wv -> vsum ==============================
    // unit u: bg = u>>6 (8), dt = u&63 (64 tiles of 16 d). 16 warps, warp = one d.
    for (int u = cta; u < 512; u += NCTA) {
        const int bg = u >> 6;
        const int dt = u & 63;
        const int d = dt * 16 + wid;

        wait_ge(&d_done2[2 * bg], 1);
        wait_ge(&d_done2[2 * bg + 1], 1);

        float* ss = spw;                        // 2*CDIM floats
        {
            const float4* src = reinterpret_cast<const float4*>(g_s + bg * 2 * CDIM);
            reinterpret_cast<float4*>(ss)[tid] = __ldcg(&src[tid]);   // 512 float4
        }
        const float4* wrow = reinterpret_cast<const float4*>(Wv + (size_t)d * CDIM);
        float4 wreg[8];
        #pragma unroll
        for (int j = 0; j < 8; j++) wreg[j] = wrow[lane + 32 * j];
        __syncthreads();

        float acc[2] = {0.f, 0.f};
        #pragma unroll
        for (int j = 0; j < 8; j++) {
            const float4 wv = wreg[j];
            #pragma unroll
            for (int q = 0; q < 2; q++) {
                const float4 sv = reinterpret_cast<const float4*>(ss + q * CDIM)[lane + 32 * j];
                acc[q] += wv.x * sv.x + wv.y * sv.y + wv.z * sv.z + wv.w * sv.w;
            }
        }
        #pragma unroll
        for (int q = 0; q < 2; q++)
            #pragma unroll
            for (int o = 16; o; o >>= 1)
                acc[q] += __shfl_xor_sync(0xFFFFFFFFu, acc[q], o);

        if (lane == 0) {
            const float bs = (float)NPOS * bv[d];
            #pragma unroll
            for (int q = 0; q < 2; q++)
                g_vsum[(bg * 2 + q) * CDIM + d] = acc[q] + bs;
        }
        __syncthreads();                        // ss reuse safety before next unit
        publish(&d_done3[bg]);
    }

    // ===================== Stage 4: GEMV Wo + broadcast store ====================
    for (int v = cta; v < 512; v += NCTA) {
        const int bg = v >> 6;
        const int dt = v & 63;
        const int d = dt * 16 + wid;

        wait_ge(&d_done3[bg], 64);

        float* ss = spw;
        {
            const float4* src = reinterpret_cast<const float4*>(g_vsum + bg * 2 * CDIM);
            reinterpret_cast<float4*>(ss)[tid] = __ldcg(&src[tid]);
        }
        const float4* wrow = reinterpret_cast<const float4*>(Wo + (size_t)d * CDIM);
        float4 wreg[8];
        #pragma unroll
        for (int j = 0; j < 8; j++) wreg[j] = wrow[lane + 32 * j];
        __syncthreads();

        float acc[2] = {0.f, 0.f};
        #pragma unroll
        for (int j = 0; j < 8; j++) {
            const float4 wv = wreg[j];
            #pragma unroll
            for (int q = 0; q < 2; q++) {
                const float4 sv = reinterpret_cast<const float4*>(ss + q * CDIM)[lane + 32 * j];
                acc[q] += wv.x * sv.x + wv.y * sv.y + wv.z * sv.z + wv.w * sv.w;
            }
        }
        // Butterfly: every lane ends with the full sum -> whole warp streams stores.
        #pragma unroll
        for (int q = 0; q < 2; q++)
            #pragma unroll
            for (int o = 16; o; o >>= 1)
                acc[q] += __shfl_xor_sync(0xFFFFFFFFu, acc[q], o);

        const float bs = bo[d];
        #pragma unroll
        for (int q = 0; q < 2; q++) {
            const float val = acc[q] + bs;
            const float4 vv = make_float4(val, val, val, val);
            float4* row = reinterpret_cast<float4*>(
                out + ((size_t)((bg * 2 + q) * CDIM + d)) * NPOS);
            #pragma unroll
            for (int t = 0; t < 8; t++) __stcs(&row[lane + 32 * t], vv);
        }
        __syncthreads();                        // ss reuse safety before next unit
    }

    // ===================== Epilogue: last CTA resets counters ====================
    if (tid == 0) {
        __threadfence();
        const int old = atomicAdd(&d_done4, 1);
        if (old == NCTA - 1) {
            #pragma unroll
            for (int i = 0; i < BSZ; i++) { d_done1[i] = 0; d_done2[i] = 0; }
            #pragma unroll
            for (int i = 0; i < 8; i++) d_done3[i] = 0;
            d_done4 = 0;
            __threadfence();
        }
    }
}

extern "C" void kernel_launch(void* const* d_in, const int* in_sizes, int n_in,
                              void* d_out, int out_size) {
    const float* x     = (const float*)d_in[0];
    const float* gamma = (const float*)d_in[1];
    const float* beta  = (const float*)d_in[2];
    // d_in[3..6] = Wq,bq,Wk,bk : provably unused (softmax rows sum to 1).
    const float* Wv    = (const float*)d_in[7];
    const float* bv    = (const float*)d_in[8];
    const float* Wo    = (const float*)d_in[9];
    const float* bo    = (const float*)d_in[10];
    float* out = (float*)d_out;

    mega<<<NCTA, NTHR>>>(x, gamma, beta, Wv, bv, Wo, bo, out);
}

// round 17
// speedup vs baseline: 1.2023x; 1.2023x over previous
#include <cuda_runtime.h>

// Attention_72447508349519 — algebraic collapse:
//   softmax rows sum to 1 and einsum('bqk,bvd->bqd') contracts k and v
//   independently, so out[b,q,d] = sum_n v[b,n,d] for every q.
//   Pipeline (R10 structure): k1 (stats+weighted colsums, __ldcs x) ->
//   k2 (fold) -> k3 (GEMV Wv) -> k4 (GEMV Wo + 64MB broadcast store).
//   R17 cache policy (ONE change vs R10): k4's output stores are DEFAULT
//   policy (not __stcs). The graph loop rewrites the SAME out buffer every
//   replay; default-policy lines stay L2-resident and each replay's stores
//   become WRITE-HITS on dirty lines — no allocate, no eviction, no DRAM
//   drain. x stays __ldcs (streaming, self-victimizing) so out+W keep their
//   L2 residency. L2 budget: out 64MB + W 8MB + P churn ~8MB < 126MB.
// Unused inputs: Wq,bq,Wk,bk.

#define BSZ   16
#define CDIM  1024
#define NPOS  1024
#define NGRP  32
#define GROWS 32
#define EPS   1e-5f

__device__ float g_P[BSZ * NGRP * CDIM];
__device__ float g_mean[BSZ * NGRP];
__device__ float g_rstd[BSZ * NGRP];
__device__ float g_s[BSZ * CDIM];
__device__ float g_vsum[BSZ * CDIM];

// ---------------------------------------------------------------------------
// k1 (R10-proven): per (b,g) CTA, one pass over the 1024x32 slab of x.
// fj/gq lane mapping: warp = 4 rows x 8 float4 slots -> every LDG.128 covers
// exactly 4 fully-used 128B lines. Block 512, MLP=8 load batches.
// x loads / P stores streaming (evict-first).
// ---------------------------------------------------------------------------
#define PPITCH 1028   // bank = (4*fj + gq) mod 32 -> all 32 lanes distinct

__global__ __launch_bounds__(512) void k1_stats(const float* __restrict__ x,
                                                const float* __restrict__ gamma) {
    const int b = blockIdx.x >> 5;
    const int g = blockIdx.x & 31;
    const int tid = threadIdx.x;

    __shared__ float sg[GROWS];
    __shared__ float spw[8 * PPITCH];
    __shared__ float reds[16], redq[16];

    if (tid < GROWS) sg[tid] = gamma[g * GROWS + tid];
    __syncthreads();

    const int fj = tid & 7;    // float4 slot within the 32-float group row
    const int gq = tid >> 3;   // channel base (c = gq + 64*k), 0..63
    const float w0 = sg[fj * 4 + 0], w1 = sg[fj * 4 + 1];
    const float w2 = sg[fj * 4 + 2], w3 = sg[fj * 4 + 3];

    const float* xb = x + (size_t)b * CDIM * NPOS + g * GROWS;
    float* mypw = spw + fj * PPITCH;

    float tsum = 0.f, tsq = 0.f;
    #pragma unroll
    for (int k0 = 0; k0 < 16; k0 += 8) {
        float4 t[8];
        #pragma unroll
        for (int i = 0; i < 8; i++) {
            const int c = gq + 64 * (k0 + i);
            t[i] = __ldcs(&reinterpret_cast<const float4*>(xb + (size_t)c * NPOS)[fj]);
        }
        #pragma unroll
        for (int i = 0; i < 8; i++) {
            const int c = gq + 64 * (k0 + i);
            const float4 v = t[i];
            tsum += (v.x + v.y) + (v.z + v.w);
            tsq  += (v.x * v.x + v.y * v.y) + (v.z * v.z + v.w * v.w);
            mypw[c] = w0 * v.x + w1 * v.y + w2 * v.z + w3 * v.w;
        }
    }
    __syncthreads();

    // Fold the 8 fj-partials per channel (conflict-free, stride-1 c).
    float* Pout = g_P + (b * NGRP + g) * CDIM;
    #pragma unroll
    for (int m = 0; m < 2; m++) {
        const int c = tid + 512 * m;
        float acc = spw[c];
        #pragma unroll
        for (int f = 1; f < 8; f++) acc += spw[f * PPITCH + c];
        __stcs(&Pout[c], acc);
    }

    // Block reduction for mean/rstd.
    #pragma unroll
    for (int o = 16; o; o >>= 1) {
        tsum += __shfl_xor_sync(0xFFFFFFFFu, tsum, o);
        tsq  += __shfl_xor_sync(0xFFFFFFFFu, tsq,  o);
    }
    const int wid = tid >> 5, lane = tid & 31;
    if (lane == 0) { reds[wid] = tsum; redq[wid] = tsq; }
    __syncthreads();
    if (tid == 0) {
        float S = 0.f, Q = 0.f;
        #pragma unroll
        for (int w = 0; w < 16; w++) { S += reds[w]; Q += redq[w]; }
        const float inv = 1.f / (float)(GROWS * CDIM);
        const float m = S * inv;
        const float var = Q * inv - m * m;
        g_mean[b * NGRP + g] = m;
        g_rstd[b * NGRP + g] = rsqrtf(var + EPS);
    }
}

// ---------------------------------------------------------------------------
// k2: s[b,c] = sum_g rstd[b,g]*(P[b,g,c] - mean[b,g]*Gam_g) + sum_n beta[n]
// ---------------------------------------------------------------------------
__global__ __launch_bounds__(1024) void k2_colsum(const float* __restrict__ gamma,
                                                  const float* __restrict__ beta) {
    const int b = blockIdx.x;
    const int tid = threadIdx.x;

    __shared__ float sgam[CDIM];
    __shared__ float sGam[NGRP];
    __shared__ float sm[NGRP], sr[NGRP];
    __shared__ float redb[32];
    __shared__ float sB;

    sgam[tid] = gamma[tid];
    float bb = beta[tid];
    #pragma unroll
    for (int o = 16; o; o >>= 1) bb += __shfl_xor_sync(0xFFFFFFFFu, bb, o);
    const int wid = tid >> 5, lane = tid & 31;
    if (lane == 0) redb[wid] = bb;
    if (tid < NGRP) { sm[tid] = g_mean[b * NGRP + tid]; sr[tid] = g_rstd[b * NGRP + tid]; }
    __syncthreads();

    if (tid < NGRP) {
        float t = 0.f;
        #pragma unroll
        for (int j = 0; j < GROWS; j++) t += sgam[tid * GROWS + j];
        sGam[tid] = t;
    }
    if (tid == 0) {
        float t = 0.f;
        #pragma unroll
        for (int w = 0; w < 32; w++) t += redb[w];
        sB = t;
    }
    __syncthreads();

    float acc = sB;
    const float* Pb = g_P + b * NGRP * CDIM + tid;
    #pragma unroll
    for (int g = 0; g < NGRP; g++)
        acc += sr[g] * (__ldcs(&Pb[g * CDIM]) - sm[g] * sGam[g]);
    g_s[b * CDIM + tid] = acc;
}

// ---------------------------------------------------------------------------
// k3: vsum[b,d] = s[b,:].Wv[d,:] + 1024*bv[d]
// grid (128 d-tiles, 8 batch-groups) = 1024 CTAs, 256 thr, 8KB smem.
// One warp per d, 2-batch accumulators; full W row batched into registers.
// ---------------------------------------------------------------------------
__global__ __launch_bounds__(256) void k3_gemv_v(const float* __restrict__ W,
                                                 const float* __restrict__ bias) {
    const int bg = blockIdx.y;           // batches 2*bg, 2*bg+1
    const int tid = threadIdx.x;
    const int wid = tid >> 5, lane = tid & 31;
    const int d = blockIdx.x * 8 + wid;

    __shared__ float ss[2 * CDIM];       // 8 KB

    const float4* wrow = reinterpret_cast<const float4*>(W + (size_t)d * CDIM);
    float4 wreg[8];
    #pragma unroll
    for (int j = 0; j < 8; j++) wreg[j] = wrow[lane + 32 * j];

    {
        const float4* src = reinterpret_cast<const float4*>(g_s + bg * 2 * CDIM);
        float4* dst = reinterpret_cast<float4*>(ss);
        #pragma unroll
        for (int m = 0; m < 2; m++) dst[tid + 256 * m] = src[tid + 256 * m];
    }
    __syncthreads();

    float acc[2] = {0.f, 0.f};
    #pragma unroll
    for (int j = 0; j < 8; j++) {
        const float4 wv = wreg[j];
        #pragma unroll
        for (int q = 0; q < 2; q++) {
            const float4 sv = reinterpret_cast<const float4*>(ss + q * CDIM)[lane + 32 * j];
            acc[q] += wv.x * sv.x + wv.y * sv.y + wv.z * sv.z + wv.w * sv.w;
        }
    }
    #pragma unroll
    for (int q = 0; q < 2; q++)
        #pragma unroll
        for (int o = 16; o; o >>= 1)
            acc[q] += __shfl_xor_sync(0xFFFFFFFFu, acc[q], o);

    if (lane == 0) {
        const float bs = (float)NPOS * bias[d];
        #pragma unroll
        for (int q = 0; q < 2; q++)
            g_vsum[(bg * 2 + q) * CDIM + d] = acc[q] + bs;
    }
}

// ---------------------------------------------------------------------------
// k4: y[b,d] = vsum[b,:].Wo[d,:] + bo[d], fused with the 64MB broadcast
// store out[b,d,:] = y[b,d] — DEFAULT-policy stores (R17 change): out lines
// stay L2-resident across replays, so steady-state stores are write-hits on
// dirty lines (no allocate, no eviction, no DRAM drain). grid (128, 8).
// ---------------------------------------------------------------------------
__global__ __launch_bounds__(256) void k4_gemv_o_bcast(const float* __restrict__ W,
                                                       const float* __restrict__ bias,
                                                       float* __restrict__ out) {
    const int bg = blockIdx.y;           // batches 2*bg, 2*bg+1
    const int tid = threadIdx.x;
    const int wid = tid >> 5, lane = tid & 31;
    const int d = blockIdx.x * 8 + wid;

    __shared__ float ss[2 * CDIM];       // 8 KB

    const float4* wrow = reinterpret_cast<const float4*>(W + (size_t)d * CDIM);
    float4 wreg[8];
    #pragma unroll
    for (int j = 0; j < 8; j++) wreg[j] = wrow[lane + 32 * j];

    {
        const float4* src = reinterpret_cast<const float4*>(g_vsum + bg * 2 * CDIM);
        float4* dst = reinterpret_cast<float4*>(ss);
        #pragma unroll
        for (int m = 0; m < 2; m++) dst[tid + 256 * m] = src[tid + 256 * m];
    }
    __syncthreads();

    float acc[2] = {0.f, 0.f};
    #pragma unroll
    for (int j = 0; j < 8; j++) {
        const float4 wv = wreg[j];
        #pragma unroll
        for (int q = 0; q < 2; q++) {
            const float4 sv = reinterpret_cast<const float4*>(ss + q * CDIM)[lane + 32 * j];
            acc[q] += wv.x * sv.x + wv.y * sv.y + wv.z * sv.z + wv.w * sv.w;
        }
    }
    // Butterfly: every lane ends with the full sum -> whole warp streams stores.
    #pragma unroll
    for (int q = 0; q < 2; q++)
        #pragma unroll
        for (int o = 16; o; o >>= 1)
            acc[q] += __shfl_xor_sync(0xFFFFFFFFu, acc[q], o);

    const float bs = bias[d];
    #pragma unroll
    for (int q = 0; q < 2; q++) {
        const float v = acc[q] + bs;
        const float4 vv = make_float4(v, v, v, v);
        float4* row = reinterpret_cast<float4*>(
            out + ((size_t)((bg * 2 + q) * CDIM + d)) * NPOS);
        #pragma unroll
        for (int t = 0; t < 8; t++) row[lane + 32 * t] = vv;   // default policy
    }
}

extern "C" void kernel_launch(void* const* d_in, const int* in_sizes, int n_in,
                              void* d_out, int out_size) {
    const float* x     = (const float*)d_in[0];
    const float* gamma = (const float*)d_in[1];
    const float* beta  = (const float*)d_in[2];
    // d_in[3..6] = Wq,bq,Wk,bk : provably unused (softmax rows sum to 1).
    const float* Wv    = (const float*)d_in[7];
    const float* bv    = (const float*)d_in[8];
    const float* Wo    = (const float*)d_in[9];
    const float* bo    = (const float*)d_in[10];
    float* out = (float*)d_out;

    k1_stats<<<BSZ * NGRP, 512>>>(x, gamma);
    k2_colsum<<<BSZ, 1024>>>(gamma, beta);
    k3_gemv_v<<<dim3(CDIM / 8, 8), 256>>>(Wv, bv);
    k4_gemv_o_bcast<<<dim3(CDIM / 8, 8), 256>>>(Wo, bo, out);
}